// round 4
// baseline (speedup 1.0000x reference)
#include <cuda_runtime.h>
#include <math.h>

// Problem dims (fixed by the dataset)
#define BATCH 32
#define TK    196
#define ROWS  (BATCH * TK)   // 6272 = 49 * 128
#define GFD   4096
#define DH    1024

// ---------------------------------------------------------------------------
// Scratch (allocation-free rule: __device__ globals)
// ---------------------------------------------------------------------------
__device__ __align__(16) float g_W1[GFD * DH];       // Wg @ Gs      (16 MB)
__device__ __align__(16) float g_b1[DH];             // bg @ Gs + bgs
__device__ __align__(16) float g_gstar[ROWS * DH];   // X @ W1 + b1  (25.7 MB)
__device__ __align__(16) float g_wgs[ROWS * DH];     // g_star @ Wgs (25.7 MB)
__device__ __align__(16) float g_dec[BATCH * DH];
__device__ __align__(16) float g_scores[ROWS];
__device__ __align__(16) float g_alpha[ROWS];

// ---------------------------------------------------------------------------
// Packed fp32x2 FMA (sm_100+): 2 FMA lanes per fma-pipe issue slot.
// ptxas never auto-fuses this; only reachable via PTX.
// ---------------------------------------------------------------------------
__device__ __forceinline__ float2 ffma2(float2 d, float2 a, float2 b) {
    unsigned long long dd = *reinterpret_cast<unsigned long long*>(&d);
    unsigned long long aa = *reinterpret_cast<unsigned long long*>(&a);
    unsigned long long bb = *reinterpret_cast<unsigned long long*>(&b);
    asm("fma.rn.f32x2 %0, %1, %2, %0;" : "+l"(dd) : "l"(aa), "l"(bb));
    return *reinterpret_cast<float2*>(&dd);
}

// ---------------------------------------------------------------------------
// Tiled SGEMM: C[M,N] = A[M,K] @ B[K,N] (+ bias), all row-major.
// BM=BN=128, BK=16, 8x8 per-thread microtile, f32x2 inner product,
// double-buffered SMEM pipeline (one barrier per K-tile).
// Requires M%128==0, N%128==0, K%16==0 (true for all 3 call sites).
// ---------------------------------------------------------------------------
#define BM 128
#define BN 128
#define BK 16
#define TM 8
#define TN 8

__global__ __launch_bounds__(256)
void sgemm_f32x2(int M, int N, int K,
                 const float* __restrict__ A,
                 const float* __restrict__ Bm,
                 const float* __restrict__ bias,   // may be nullptr
                 float* __restrict__ C)
{
    __shared__ float As[2][BK][BM];   // transposed: As[buf][k][m]
    __shared__ float Bs[2][BK][BN];

    const int cRow = blockIdx.y;
    const int cCol = blockIdx.x;
    const int tid  = threadIdx.x;

    const int threadCol = tid % (BN / TN);   // 0..15
    const int threadRow = tid / (BN / TN);   // 0..15

    const float* Ablk = A  + (size_t)cRow * BM * K;
    const float* Bblk = Bm + cCol * BN;

    const int innerRowA = tid / (BK / 4);    // 0..63  (2 row passes of 64)
    const int innerColA = tid % (BK / 4);    // 0..3   (float4 along K)
    const int innerRowB = tid / (BN / 4);    // 0..7   (2 row passes of 8)
    const int innerColB = tid % (BN / 4);    // 0..31  (float4 along N)

    float2 acc[TM][TN / 2];
#pragma unroll
    for (int i = 0; i < TM; i++)
#pragma unroll
        for (int j = 0; j < TN / 2; j++) acc[i][j] = make_float2(0.f, 0.f);

    const int numTiles = K / BK;

    // ---- prologue: load tile 0 into buffer 0 ----
    {
#pragma unroll
        for (int p = 0; p < 2; p++) {
            int r = innerRowA + p * 64;
            float4 t = *reinterpret_cast<const float4*>(
                &Ablk[(size_t)r * K + innerColA * 4]);
            As[0][innerColA * 4 + 0][r] = t.x;
            As[0][innerColA * 4 + 1][r] = t.y;
            As[0][innerColA * 4 + 2][r] = t.z;
            As[0][innerColA * 4 + 3][r] = t.w;
        }
#pragma unroll
        for (int p = 0; p < 2; p++) {
            int r = innerRowB + p * 8;
            *reinterpret_cast<float4*>(&Bs[0][r][innerColB * 4]) =
                *reinterpret_cast<const float4*>(
                    &Bblk[(size_t)r * N + innerColB * 4]);
        }
    }
    __syncthreads();

    int cur = 0;
    for (int t = 0; t < numTiles; ++t) {
        const int nxt = cur ^ 1;
        float4 pa[2], pb[2];
        const bool more = (t + 1 < numTiles);

        // ---- prefetch tile t+1 into registers (overlaps with compute) ----
        if (more) {
            int bk = (t + 1) * BK;
#pragma unroll
            for (int p = 0; p < 2; p++)
                pa[p] = *reinterpret_cast<const float4*>(
                    &Ablk[(size_t)(innerRowA + p * 64) * K + bk + innerColA * 4]);
#pragma unroll
            for (int p = 0; p < 2; p++)
                pb[p] = *reinterpret_cast<const float4*>(
                    &Bblk[(size_t)(bk + innerRowB + p * 8) * N + innerColB * 4]);
        }

        // ---- compute on buffer `cur` ----
#pragma unroll
        for (int k = 0; k < BK; ++k) {
            float  regM[TM];
            float2 regN[TN / 2];
#pragma unroll
            for (int i = 0; i < TM; i++) regM[i] = As[cur][k][threadRow * TM + i];
#pragma unroll
            for (int j = 0; j < TN / 2; j++)
                regN[j] = *reinterpret_cast<float2*>(&Bs[cur][k][threadCol * TN + 2 * j]);
#pragma unroll
            for (int i = 0; i < TM; i++) {
                float2 am = make_float2(regM[i], regM[i]);
#pragma unroll
                for (int j = 0; j < TN / 2; j++)
                    acc[i][j] = ffma2(acc[i][j], am, regN[j]);
            }
        }

        // ---- stage prefetched tile into buffer `nxt` ----
        if (more) {
#pragma unroll
            for (int p = 0; p < 2; p++) {
                int r = innerRowA + p * 64;
                As[nxt][innerColA * 4 + 0][r] = pa[p].x;
                As[nxt][innerColA * 4 + 1][r] = pa[p].y;
                As[nxt][innerColA * 4 + 2][r] = pa[p].z;
                As[nxt][innerColA * 4 + 3][r] = pa[p].w;
            }
#pragma unroll
            for (int p = 0; p < 2; p++) {
                int r = innerRowB + p * 8;
                *reinterpret_cast<float4*>(&Bs[nxt][r][innerColB * 4]) = pb[p];
            }
        }
        __syncthreads();
        cur = nxt;
    }

    // ---- epilogue: optional bias, float4 stores ----
    float bv[TN];
#pragma unroll
    for (int j = 0; j < TN; j++) bv[j] = 0.f;
    if (bias) {
#pragma unroll
        for (int j = 0; j < TN; j++)
            bv[j] = bias[cCol * BN + threadCol * TN + j];
    }

    float* Cp = C + (size_t)(cRow * BM + threadRow * TM) * N + cCol * BN + threadCol * TN;
#pragma unroll
    for (int i = 0; i < TM; i++) {
        float4 o0 = make_float4(acc[i][0].x + bv[0], acc[i][0].y + bv[1],
                                acc[i][1].x + bv[2], acc[i][1].y + bv[3]);
        float4 o1 = make_float4(acc[i][2].x + bv[4], acc[i][2].y + bv[5],
                                acc[i][3].x + bv[6], acc[i][3].y + bv[7]);
        *reinterpret_cast<float4*>(&Cp[(size_t)i * N])     = o0;
        *reinterpret_cast<float4*>(&Cp[(size_t)i * N + 4]) = o1;
    }
}

// ---------------------------------------------------------------------------
// b1[j] = sum_k bg[k] * Gs[k,j] + bgs[j]     (DH outputs, K=GFD)
// ---------------------------------------------------------------------------
__global__ void b1_kernel(const float* __restrict__ bg,
                          const float* __restrict__ Gs,
                          const float* __restrict__ bgs,
                          float* __restrict__ b1)
{
    int j = blockIdx.x * blockDim.x + threadIdx.x;   // 0..1023
    float acc = bgs[j];
#pragma unroll 8
    for (int k = 0; k < GFD; k++)
        acc += bg[k] * Gs[(size_t)k * DH + j];
    b1[j] = acc;
}

// ---------------------------------------------------------------------------
// dec[b,j] = sum_k s[b,k] * Wdec[k,j] + bdec[j]   (one block per batch row)
// ---------------------------------------------------------------------------
__global__ void dec_kernel(const float* __restrict__ s,
                           const float* __restrict__ Wdec,
                           const float* __restrict__ bdec,
                           float* __restrict__ dec)
{
    int b = blockIdx.x;
    __shared__ float sr[DH];
    for (int k = threadIdx.x; k < DH; k += blockDim.x)
        sr[k] = s[(size_t)b * DH + k];
    __syncthreads();

    for (int j = threadIdx.x; j < DH; j += blockDim.x) {
        float acc = bdec[j];
#pragma unroll 8
        for (int k = 0; k < DH; k++)
            acc += sr[k] * Wdec[(size_t)k * DH + j];
        dec[(size_t)b * DH + j] = acc;
    }
}

// ---------------------------------------------------------------------------
// scores[row] = sum_j tanh(w[row,j] + dec[b,j] + cov[row]) * v[j]
// One block (256 threads) per row.
// ---------------------------------------------------------------------------
__global__ void score_kernel(const float* __restrict__ w,
                             const float* __restrict__ dec,
                             const float* __restrict__ cov,
                             const float* __restrict__ v,
                             float* __restrict__ scores)
{
    int row = blockIdx.x;
    int b   = row / TK;
    float c = cov[row];
    const float* wr = w   + (size_t)row * DH;
    const float* db = dec + (size_t)b   * DH;

    float acc = 0.f;
    for (int j = threadIdx.x; j < DH; j += blockDim.x)
        acc += tanhf(wr[j] + db[j] + c) * v[j];

    // warp reduce then cross-warp
    for (int off = 16; off > 0; off >>= 1)
        acc += __shfl_xor_sync(0xffffffffu, acc, off);

    __shared__ float red[8];
    if ((threadIdx.x & 31) == 0) red[threadIdx.x >> 5] = acc;
    __syncthreads();
    if (threadIdx.x == 0) {
        float s = 0.f;
#pragma unroll
        for (int i = 0; i < 8; i++) s += red[i];
        scores[row] = s;
    }
}

// ---------------------------------------------------------------------------
// Per-batch softmax over TK regions; writes alpha (scratch + out) and
// coverage_new = cov + alpha (out). One block per batch.
// ---------------------------------------------------------------------------
__global__ void softmax_kernel(const float* __restrict__ scores,
                               const float* __restrict__ cov,
                               float* __restrict__ alpha,
                               float* __restrict__ out_cov,
                               float* __restrict__ out_alpha)
{
    int b = blockIdx.x;
    int t = threadIdx.x;
    __shared__ float sh[256];

    float s = (t < TK) ? scores[b * TK + t] : -3.402823e38f;
    sh[t] = s;
    __syncthreads();
#pragma unroll
    for (int st = 128; st > 0; st >>= 1) {
        if (t < st) sh[t] = fmaxf(sh[t], sh[t + st]);
        __syncthreads();
    }
    float mx = sh[0];
    __syncthreads();

    float e = (t < TK) ? expf(s - mx) : 0.f;
    sh[t] = e;
    __syncthreads();
#pragma unroll
    for (int st = 128; st > 0; st >>= 1) {
        if (t < st) sh[t] += sh[t + st];
        __syncthreads();
    }
    float inv = 1.f / sh[0];

    if (t < TK) {
        float a = e * inv;
        alpha[b * TK + t]     = a;
        out_alpha[b * TK + t] = a;
        out_cov[b * TK + t]   = cov[b * TK + t] + a;
    }
}

// ---------------------------------------------------------------------------
// c_img[b,d] = sum_t alpha[b,t] * g_star[b,t,d].  One block per batch.
// ---------------------------------------------------------------------------
__global__ void context_kernel(const float* __restrict__ gstar,
                               const float* __restrict__ alpha,
                               float* __restrict__ cimg)
{
    int b = blockIdx.x;
    __shared__ float a[TK];
    for (int t = threadIdx.x; t < TK; t += blockDim.x)
        a[t] = alpha[b * TK + t];
    __syncthreads();

    for (int d = threadIdx.x; d < DH; d += blockDim.x) {
        const float* g = gstar + (size_t)b * TK * DH + d;
        float acc = 0.f;
#pragma unroll 7
        for (int t = 0; t < TK; t++)
            acc += a[t] * g[(size_t)t * DH];
        cimg[(size_t)b * DH + d] = acc;
    }
}

// ---------------------------------------------------------------------------
// Launcher
// Inputs (metadata order):
//  0 global_features [32,196,4096]  1 s_t_hat [32,1024]  2 coverage_img [32,196,1]
//  3 Wg [4096,4096]  4 bg [4096]  5 Gs [4096,1024]  6 bgs [1024]
//  7 Wgs [1024,1024] 8 Wdec [1024,1024] 9 bdec [1024] 10 v [1024,1]
// Output: c_img [32*1024] | coverage_new [32*196] | alpha [32*196]
// ---------------------------------------------------------------------------
extern "C" void kernel_launch(void* const* d_in, const int* in_sizes, int n_in,
                              void* d_out, int out_size)
{
    const float* X    = (const float*)d_in[0];
    const float* sth  = (const float*)d_in[1];
    const float* cov  = (const float*)d_in[2];
    const float* Wg   = (const float*)d_in[3];
    const float* bg   = (const float*)d_in[4];
    const float* Gs   = (const float*)d_in[5];
    const float* bgs  = (const float*)d_in[6];
    const float* Wgs  = (const float*)d_in[7];
    const float* Wdec = (const float*)d_in[8];
    const float* bdec = (const float*)d_in[9];
    const float* v    = (const float*)d_in[10];

    float* out       = (float*)d_out;
    float* out_cimg  = out;
    float* out_cov   = out + BATCH * DH;
    float* out_alpha = out + BATCH * DH + BATCH * TK;

    float *W1, *b1, *gstar, *wgs, *dec, *scores, *alpha;
    cudaGetSymbolAddress((void**)&W1,     g_W1);
    cudaGetSymbolAddress((void**)&b1,     g_b1);
    cudaGetSymbolAddress((void**)&gstar,  g_gstar);
    cudaGetSymbolAddress((void**)&wgs,    g_wgs);
    cudaGetSymbolAddress((void**)&dec,    g_dec);
    cudaGetSymbolAddress((void**)&scores, g_scores);
    cudaGetSymbolAddress((void**)&alpha,  g_alpha);

    // 1) W1 = Wg @ Gs                      [4096,1024], K=4096  (34.4 GF)
    sgemm_f32x2<<<dim3(DH / BN, GFD / BM), 256>>>(GFD, DH, GFD, Wg, Gs, nullptr, W1);
    // 2) b1 = bg @ Gs + bgs
    b1_kernel<<<DH / 256, 256>>>(bg, Gs, bgs, b1);
    // 3) g_star = X @ W1 + b1              [6272,1024], K=4096  (52.6 GF)
    sgemm_f32x2<<<dim3(DH / BN, ROWS / BM), 256>>>(ROWS, DH, GFD, X, W1, b1, gstar);
    // 4) w = g_star @ Wgs                  [6272,1024], K=1024  (13.2 GF)
    sgemm_f32x2<<<dim3(DH / BN, ROWS / BM), 256>>>(ROWS, DH, DH, gstar, Wgs, nullptr, wgs);
    // 5) dec = s_t_hat @ Wdec + bdec
    dec_kernel<<<BATCH, 256>>>(sth, Wdec, bdec, dec);
    // 6) scores = tanh(w + dec + cov) @ v
    score_kernel<<<ROWS, 256>>>(wgs, dec, cov, v, scores);
    // 7) softmax over regions; alpha + coverage_new outputs
    softmax_kernel<<<BATCH, 256>>>(scores, cov, alpha, out_cov, out_alpha);
    // 8) c_img = alpha^T @ g_star
    context_kernel<<<BATCH, 256>>>(gstar, alpha, out_cimg);
}

// round 10
// speedup vs baseline: 1.7206x; 1.7206x over previous
#include <cuda_runtime.h>
#include <cuda_bf16.h>
#include <math.h>
#include <stdint.h>

// Problem dims (fixed by the dataset)
#define BATCH 32
#define TK    196
#define ROWS  (BATCH * TK)   // 6272 = 49 * 128
#define GFD   4096
#define DH    1024

// ---------------------------------------------------------------------------
// Scratch (allocation-free rule: __device__ globals)
// ---------------------------------------------------------------------------
__device__ __align__(16) float g_W1[GFD * DH];       // Wg @ Gs (fp32)
__device__ __align__(16) float g_b1[DH];             // bg @ Gs + bgs
__device__ __align__(16) float g_gstar[ROWS * DH];   // X @ W1 + b1 (fp32)
__device__ __align__(16) float g_wgs[ROWS * DH];     // g_star @ Wgs (fp32)
__device__ __align__(16) float g_dec[BATCH * DH];
__device__ __align__(16) float g_scores[ROWS];
__device__ __align__(16) float g_alpha[ROWS];

// split-bf16 operands
__device__ __align__(16) __nv_bfloat16 g_Xhi[ROWS * GFD];
__device__ __align__(16) __nv_bfloat16 g_Xlo[ROWS * GFD];
__device__ __align__(16) __nv_bfloat16 g_Wghi[GFD * GFD];
__device__ __align__(16) __nv_bfloat16 g_Wglo[GFD * GFD];
__device__ __align__(16) __nv_bfloat16 g_GsThi[DH * GFD];   // Gs^T  [DH, GFD]
__device__ __align__(16) __nv_bfloat16 g_GsTlo[DH * GFD];
__device__ __align__(16) __nv_bfloat16 g_W1Thi[DH * GFD];   // W1^T  [DH, GFD]
__device__ __align__(16) __nv_bfloat16 g_W1Tlo[DH * GFD];
__device__ __align__(16) __nv_bfloat16 g_ghi[ROWS * DH];    // gstar split
__device__ __align__(16) __nv_bfloat16 g_glo[ROWS * DH];
__device__ __align__(16) __nv_bfloat16 g_WgsThi[DH * DH];   // Wgs^T [DH, DH]
__device__ __align__(16) __nv_bfloat16 g_WgsTlo[DH * DH];

// ---------------------------------------------------------------------------
// Helpers (base compute_103 PTX only: mma.sync + cp.async, both sm_80+)
// ---------------------------------------------------------------------------
__device__ __forceinline__ uint32_t smem_u32(const void* p) {
    uint32_t a;
    asm("{ .reg .u64 t; cvta.to.shared.u64 t, %1; cvt.u32.u64 %0, t; }"
        : "=r"(a) : "l"(p));
    return a;
}

__device__ __forceinline__ void cp_async16(void* sptr, const void* gptr) {
    uint32_t s = smem_u32(sptr);
    asm volatile("cp.async.cg.shared.global [%0], [%1], 16;"
                 :: "r"(s), "l"(gptr) : "memory");
}
#define CP_COMMIT() asm volatile("cp.async.commit_group;" ::: "memory")
#define CP_WAIT0()  asm volatile("cp.async.wait_group 0;" ::: "memory")

// m16n8k16 row.col bf16 -> f32
#define MMA16816(c, a, b) \
    asm volatile( \
        "mma.sync.aligned.m16n8k16.row.col.f32.bf16.bf16.f32 " \
        "{%0,%1,%2,%3}, {%4,%5,%6,%7}, {%8,%9}, {%0,%1,%2,%3};" \
        : "+f"((c)[0]), "+f"((c)[1]), "+f"((c)[2]), "+f"((c)[3]) \
        : "r"((a)[0]), "r"((a)[1]), "r"((a)[2]), "r"((a)[3]), \
          "r"((b)[0]), "r"((b)[1]))

// ---------------------------------------------------------------------------
// Tensor-core split-bf16 GEMM: C[M,N] = Ahi/lo[M,K] @ (Bhi/lo[N,K])^T (+bias)
// 128x128 tile/CTA, 8 warps (2x4) each m64xn32, BK=32, cp.async double buffer.
// PAD=40 elems/row: 16B-aligned rows, conflict-free fragment loads.
// M,N % 128 == 0, K % 32 == 0.
// ---------------------------------------------------------------------------
#define PAD 40
#define TILE_ELEMS (128 * PAD)          // one 128x32 tile (padded)
#define STAGE_ELEMS (4 * TILE_ELEMS)    // Ahi, Alo, Bhi, Blo
#define MM_SMEM (2 * STAGE_ELEMS * 2)   // bytes, double buffered = 81920

__global__ __launch_bounds__(256)
void mma_gemm(int M, int N, int K,
              const __nv_bfloat16* __restrict__ Ahi, const __nv_bfloat16* __restrict__ Alo,
              const __nv_bfloat16* __restrict__ Bhi, const __nv_bfloat16* __restrict__ Blo,
              const float* __restrict__ bias, float* __restrict__ C)
{
    extern __shared__ __nv_bfloat16 sm[];
    const int tid  = threadIdx.x;
    const int wid  = tid >> 5;
    const int lane = tid & 31;
    const int g    = lane >> 2;      // 0..7
    const int tig  = lane & 3;       // 0..3
    const int wm   = wid >> 2;       // 0..1  (warp row)
    const int wn   = wid & 3;        // 0..3  (warp col)
    const int m0 = blockIdx.y * 128;
    const int n0 = blockIdx.x * 128;
    const int seg = tid & 3;         // 16B segment within 32-elem K row
    const int lr  = tid >> 2;        // 0..63 (2 passes of 64 rows)

    float acc[4][4][4];
#pragma unroll
    for (int i = 0; i < 4; i++)
#pragma unroll
        for (int j = 0; j < 4; j++)
#pragma unroll
            for (int q = 0; q < 4; q++) acc[i][j][q] = 0.f;

    const int nCh = K / 32;

#define ISSUE(c_, buf_) do {                                                     \
    size_t _k0 = (size_t)(c_) * 32;                                              \
    __nv_bfloat16* _st = sm + (buf_) * STAGE_ELEMS;                              \
    _Pragma("unroll")                                                            \
    for (int _p = 0; _p < 2; _p++) {                                             \
        int _r = lr + _p * 64;                                                   \
        size_t _so = (size_t)_r * PAD + seg * 8;                                 \
        size_t _ga = (size_t)(m0 + _r) * K + _k0 + seg * 8;                      \
        size_t _gb = (size_t)(n0 + _r) * K + _k0 + seg * 8;                      \
        cp_async16(_st + _so,                  Ahi + _ga);                       \
        cp_async16(_st + TILE_ELEMS + _so,     Alo + _ga);                       \
        cp_async16(_st + 2 * TILE_ELEMS + _so, Bhi + _gb);                       \
        cp_async16(_st + 3 * TILE_ELEMS + _so, Blo + _gb);                       \
    }                                                                            \
} while (0)

    ISSUE(0, 0);
    CP_COMMIT();

    for (int c = 0; c < nCh; ++c) {
        const int buf = c & 1;
        CP_WAIT0();
        __syncthreads();                 // buffer `buf` ready; prior compute done
        if (c + 1 < nCh) {
            ISSUE(c + 1, buf ^ 1);
            CP_COMMIT();
        }

        const __nv_bfloat16* sAh = sm + buf * STAGE_ELEMS;
        const __nv_bfloat16* sAl = sAh + TILE_ELEMS;
        const __nv_bfloat16* sBh = sAh + 2 * TILE_ELEMS;
        const __nv_bfloat16* sBl = sAh + 3 * TILE_ELEMS;

#pragma unroll
        for (int ks = 0; ks < 2; ks++) {
            const int kc = ks * 16 + 2 * tig;
            uint32_t ah[4][4], al[4][4], bh[4][2], bl[4][2];
#pragma unroll
            for (int mt = 0; mt < 4; mt++) {
                int r = wm * 64 + mt * 16 + g;
                ah[mt][0] = *(const uint32_t*)(sAh + (size_t)r * PAD + kc);
                ah[mt][1] = *(const uint32_t*)(sAh + (size_t)(r + 8) * PAD + kc);
                ah[mt][2] = *(const uint32_t*)(sAh + (size_t)r * PAD + kc + 8);
                ah[mt][3] = *(const uint32_t*)(sAh + (size_t)(r + 8) * PAD + kc + 8);
                al[mt][0] = *(const uint32_t*)(sAl + (size_t)r * PAD + kc);
                al[mt][1] = *(const uint32_t*)(sAl + (size_t)(r + 8) * PAD + kc);
                al[mt][2] = *(const uint32_t*)(sAl + (size_t)r * PAD + kc + 8);
                al[mt][3] = *(const uint32_t*)(sAl + (size_t)(r + 8) * PAD + kc + 8);
            }
#pragma unroll
            for (int nt = 0; nt < 4; nt++) {
                int r = wn * 32 + nt * 8 + g;
                bh[nt][0] = *(const uint32_t*)(sBh + (size_t)r * PAD + kc);
                bh[nt][1] = *(const uint32_t*)(sBh + (size_t)r * PAD + kc + 8);
                bl[nt][0] = *(const uint32_t*)(sBl + (size_t)r * PAD + kc);
                bl[nt][1] = *(const uint32_t*)(sBl + (size_t)r * PAD + kc + 8);
            }
#pragma unroll
            for (int mt = 0; mt < 4; mt++)
#pragma unroll
                for (int nt = 0; nt < 4; nt++) {
                    MMA16816(acc[mt][nt], ah[mt], bh[nt]);   // hi*hi
                    MMA16816(acc[mt][nt], ah[mt], bl[nt]);   // hi*lo
                    MMA16816(acc[mt][nt], al[mt], bh[nt]);   // lo*hi
                }
        }
        __syncthreads();   // all warps done with `buf` before it is refilled
    }
#undef ISSUE

    // Epilogue: c0=C[g][2tig], c1=C[g][2tig+1], c2=C[g+8][2tig], c3=C[g+8][2tig+1]
#pragma unroll
    for (int mt = 0; mt < 4; mt++) {
#pragma unroll
        for (int nt = 0; nt < 4; nt++) {
            int r  = m0 + wm * 64 + mt * 16 + g;
            int cc = n0 + wn * 32 + nt * 8 + 2 * tig;
            float b0 = bias ? bias[cc]     : 0.f;
            float b1 = bias ? bias[cc + 1] : 0.f;
            float2 o0 = make_float2(acc[mt][nt][0] + b0, acc[mt][nt][1] + b1);
            float2 o1 = make_float2(acc[mt][nt][2] + b0, acc[mt][nt][3] + b1);
            *reinterpret_cast<float2*>(C + (size_t)r * N + cc)       = o0;
            *reinterpret_cast<float2*>(C + (size_t)(r + 8) * N + cc) = o1;
        }
    }
}

// ---------------------------------------------------------------------------
// split fp32 -> (hi, lo) bf16, same layout. n4 = element_count / 4.
// ---------------------------------------------------------------------------
__global__ void split_kernel(const float4* __restrict__ in,
                             uint2* __restrict__ hi, uint2* __restrict__ lo, int n4)
{
    int i = blockIdx.x * blockDim.x + threadIdx.x;
    if (i >= n4) return;
    float4 v = in[i];
    float vv[4] = {v.x, v.y, v.z, v.w};
    unsigned short hs[4], ls[4];
#pragma unroll
    for (int j = 0; j < 4; j++) {
        __nv_bfloat16 h = __float2bfloat16(vv[j]);
        __nv_bfloat16 l = __float2bfloat16(vv[j] - __bfloat162float(h));
        hs[j] = *reinterpret_cast<unsigned short*>(&h);
        ls[j] = *reinterpret_cast<unsigned short*>(&l);
    }
    uint2 H, L;
    H.x = (uint32_t)hs[0] | ((uint32_t)hs[1] << 16);
    H.y = (uint32_t)hs[2] | ((uint32_t)hs[3] << 16);
    L.x = (uint32_t)ls[0] | ((uint32_t)ls[1] << 16);
    L.y = (uint32_t)ls[2] | ((uint32_t)ls[3] << 16);
    hi[i] = H;
    lo[i] = L;
}

// ---------------------------------------------------------------------------
// transpose + split: in fp32 [R,C] -> hiT/loT bf16 [C,R]
// grid (C/32, R/32), block (32, 8)
// ---------------------------------------------------------------------------
__global__ void tsplit_kernel(const float* __restrict__ in,
                              __nv_bfloat16* __restrict__ hiT,
                              __nv_bfloat16* __restrict__ loT, int R, int C)
{
    __shared__ float sh[32][33];
    int c0 = blockIdx.x * 32, r0 = blockIdx.y * 32;
    int tx = threadIdx.x, ty = threadIdx.y;
#pragma unroll
    for (int i = 0; i < 32; i += 8)
        sh[ty + i][tx] = in[(size_t)(r0 + ty + i) * C + c0 + tx];
    __syncthreads();
#pragma unroll
    for (int i = 0; i < 32; i += 8) {
        float v = sh[tx][ty + i];
        __nv_bfloat16 h = __float2bfloat16(v);
        __nv_bfloat16 l = __float2bfloat16(v - __bfloat162float(h));
        size_t o = (size_t)(c0 + ty + i) * R + r0 + tx;
        hiT[o] = h;
        loT[o] = l;
    }
}

// ---------------------------------------------------------------------------
// b1[j] = sum_k bg[k] * Gs[k,j] + bgs[j]
// ---------------------------------------------------------------------------
__global__ void b1_kernel(const float* __restrict__ bg, const float* __restrict__ Gs,
                          const float* __restrict__ bgs, float* __restrict__ b1)
{
    int j = blockIdx.x * blockDim.x + threadIdx.x;
    float acc = bgs[j];
#pragma unroll 8
    for (int k = 0; k < GFD; k++)
        acc += bg[k] * Gs[(size_t)k * DH + j];
    b1[j] = acc;
}

// ---------------------------------------------------------------------------
// dec[b,j] = s[b,:] @ Wdec[:,j] + bdec[j]   (one block per batch row)
// ---------------------------------------------------------------------------
__global__ void dec_kernel(const float* __restrict__ s, const float* __restrict__ Wdec,
                           const float* __restrict__ bdec, float* __restrict__ dec)
{
    int b = blockIdx.x;
    __shared__ float sr[DH];
    for (int k = threadIdx.x; k < DH; k += blockDim.x)
        sr[k] = s[(size_t)b * DH + k];
    __syncthreads();
    for (int j = threadIdx.x; j < DH; j += blockDim.x) {
        float acc = bdec[j];
#pragma unroll 8
        for (int k = 0; k < DH; k++)
            acc += sr[k] * Wdec[(size_t)k * DH + j];
        dec[(size_t)b * DH + j] = acc;
    }
}

// ---------------------------------------------------------------------------
// scores[row] = sum_j tanh(w[row,j] + dec[b,j] + cov[row]) * v[j]
// ---------------------------------------------------------------------------
__global__ void score_kernel(const float* __restrict__ w, const float* __restrict__ dec,
                             const float* __restrict__ cov, const float* __restrict__ v,
                             float* __restrict__ scores)
{
    int row = blockIdx.x;
    int b   = row / TK;
    float c = cov[row];
    const float* wr = w   + (size_t)row * DH;
    const float* db = dec + (size_t)b   * DH;

    float acc = 0.f;
    for (int j = threadIdx.x; j < DH; j += blockDim.x)
        acc += tanhf(wr[j] + db[j] + c) * v[j];

    for (int off = 16; off > 0; off >>= 1)
        acc += __shfl_xor_sync(0xffffffffu, acc, off);

    __shared__ float red[8];
    if ((threadIdx.x & 31) == 0) red[threadIdx.x >> 5] = acc;
    __syncthreads();
    if (threadIdx.x == 0) {
        float s = 0.f;
#pragma unroll
        for (int i = 0; i < 8; i++) s += red[i];
        scores[row] = s;
    }
}

// ---------------------------------------------------------------------------
// Per-batch softmax over TK regions; alpha + coverage_new outputs.
// ---------------------------------------------------------------------------
__global__ void softmax_kernel(const float* __restrict__ scores, const float* __restrict__ cov,
                               float* __restrict__ alpha, float* __restrict__ out_cov,
                               float* __restrict__ out_alpha)
{
    int b = blockIdx.x;
    int t = threadIdx.x;
    __shared__ float sh[256];

    float s = (t < TK) ? scores[b * TK + t] : -3.402823e38f;
    sh[t] = s;
    __syncthreads();
#pragma unroll
    for (int st = 128; st > 0; st >>= 1) {
        if (t < st) sh[t] = fmaxf(sh[t], sh[t + st]);
        __syncthreads();
    }
    float mx = sh[0];
    __syncthreads();

    float e = (t < TK) ? expf(s - mx) : 0.f;
    sh[t] = e;
    __syncthreads();
#pragma unroll
    for (int st = 128; st > 0; st >>= 1) {
        if (t < st) sh[t] += sh[t + st];
        __syncthreads();
    }
    float inv = 1.f / sh[0];

    if (t < TK) {
        float a = e * inv;
        alpha[b * TK + t]     = a;
        out_alpha[b * TK + t] = a;
        out_cov[b * TK + t]   = cov[b * TK + t] + a;
    }
}

// ---------------------------------------------------------------------------
// c_img[b,d] = sum_t alpha[b,t] * g_star[b,t,d]
// ---------------------------------------------------------------------------
__global__ void context_kernel(const float* __restrict__ gstar,
                               const float* __restrict__ alpha, float* __restrict__ cimg)
{
    int b = blockIdx.x;
    __shared__ float a[TK];
    for (int t = threadIdx.x; t < TK; t += blockDim.x)
        a[t] = alpha[b * TK + t];
    __syncthreads();

    for (int d = threadIdx.x; d < DH; d += blockDim.x) {
        const float* g = gstar + (size_t)b * TK * DH + d;
        float acc = 0.f;
#pragma unroll 7
        for (int t = 0; t < TK; t++)
            acc += a[t] * g[(size_t)t * DH];
        cimg[(size_t)b * DH + d] = acc;
    }
}

// ---------------------------------------------------------------------------
// Launcher
// Inputs (metadata order):
//  0 global_features [32,196,4096]  1 s_t_hat [32,1024]  2 coverage_img [32,196,1]
//  3 Wg [4096,4096]  4 bg [4096]  5 Gs [4096,1024]  6 bgs [1024]
//  7 Wgs [1024,1024] 8 Wdec [1024,1024] 9 bdec [1024] 10 v [1024,1]
// Output: c_img [32*1024] | coverage_new [32*196] | alpha [32*196]
// ---------------------------------------------------------------------------
extern "C" void kernel_launch(void* const* d_in, const int* in_sizes, int n_in,
                              void* d_out, int out_size)
{
    const float* X    = (const float*)d_in[0];
    const float* sth  = (const float*)d_in[1];
    const float* cov  = (const float*)d_in[2];
    const float* Wg   = (const float*)d_in[3];
    const float* bg   = (const float*)d_in[4];
    const float* Gs   = (const float*)d_in[5];
    const float* bgs  = (const float*)d_in[6];
    const float* Wgs  = (const float*)d_in[7];
    const float* Wdec = (const float*)d_in[8];
    const float* bdec = (const float*)d_in[9];
    const float* v    = (const float*)d_in[10];

    float* out       = (float*)d_out;
    float* out_cimg  = out;
    float* out_cov   = out + BATCH * DH;
    float* out_alpha = out + BATCH * DH + BATCH * TK;

    float *W1, *b1, *gstar, *wgs, *dec, *scores, *alpha;
    cudaGetSymbolAddress((void**)&W1,     g_W1);
    cudaGetSymbolAddress((void**)&b1,     g_b1);
    cudaGetSymbolAddress((void**)&gstar,  g_gstar);
    cudaGetSymbolAddress((void**)&wgs,    g_wgs);
    cudaGetSymbolAddress((void**)&dec,    g_dec);
    cudaGetSymbolAddress((void**)&scores, g_scores);
    cudaGetSymbolAddress((void**)&alpha,  g_alpha);

    __nv_bfloat16 *Xhi, *Xlo, *Wghi, *Wglo, *GsThi, *GsTlo, *W1Thi, *W1Tlo,
                  *ghi, *glo, *WgsThi, *WgsTlo;
    cudaGetSymbolAddress((void**)&Xhi,    g_Xhi);
    cudaGetSymbolAddress((void**)&Xlo,    g_Xlo);
    cudaGetSymbolAddress((void**)&Wghi,   g_Wghi);
    cudaGetSymbolAddress((void**)&Wglo,   g_Wglo);
    cudaGetSymbolAddress((void**)&GsThi,  g_GsThi);
    cudaGetSymbolAddress((void**)&GsTlo,  g_GsTlo);
    cudaGetSymbolAddress((void**)&W1Thi,  g_W1Thi);
    cudaGetSymbolAddress((void**)&W1Tlo,  g_W1Tlo);
    cudaGetSymbolAddress((void**)&ghi,    g_ghi);
    cudaGetSymbolAddress((void**)&glo,    g_glo);
    cudaGetSymbolAddress((void**)&WgsThi, g_WgsThi);
    cudaGetSymbolAddress((void**)&WgsTlo, g_WgsTlo);

    cudaFuncSetAttribute(mma_gemm, cudaFuncAttributeMaxDynamicSharedMemorySize, MM_SMEM);

    // --- operand prep ---
    split_kernel<<<(GFD * GFD / 4 + 255) / 256, 256>>>(
        (const float4*)Wg, (uint2*)Wghi, (uint2*)Wglo, GFD * GFD / 4);
    tsplit_kernel<<<dim3(DH / 32, GFD / 32), dim3(32, 8)>>>(Gs, GsThi, GsTlo, GFD, DH);
    split_kernel<<<(ROWS * GFD / 4 + 255) / 256, 256>>>(
        (const float4*)X, (uint2*)Xhi, (uint2*)Xlo, ROWS * GFD / 4);
    b1_kernel<<<DH / 256, 256>>>(bg, Gs, bgs, b1);
    tsplit_kernel<<<dim3(DH / 32, DH / 32), dim3(32, 8)>>>(Wgs, WgsThi, WgsTlo, DH, DH);

    // 1) W1 = Wg @ Gs              [4096,1024], K=4096
    mma_gemm<<<dim3(DH / 128, GFD / 128), 256, MM_SMEM>>>(
        GFD, DH, GFD, Wghi, Wglo, GsThi, GsTlo, nullptr, W1);
    tsplit_kernel<<<dim3(DH / 32, GFD / 32), dim3(32, 8)>>>(W1, W1Thi, W1Tlo, GFD, DH);

    // 2) g_star = X @ W1 + b1      [6272,1024], K=4096
    mma_gemm<<<dim3(DH / 128, ROWS / 128), 256, MM_SMEM>>>(
        ROWS, DH, GFD, Xhi, Xlo, W1Thi, W1Tlo, b1, gstar);
    split_kernel<<<(ROWS * DH / 4 + 255) / 256, 256>>>(
        (const float4*)gstar, (uint2*)ghi, (uint2*)glo, ROWS * DH / 4);

    // 3) w = g_star @ Wgs          [6272,1024], K=1024
    mma_gemm<<<dim3(DH / 128, ROWS / 128), 256, MM_SMEM>>>(
        ROWS, DH, DH, ghi, glo, WgsThi, WgsTlo, nullptr, wgs);

    // 4) epilogue chain
    dec_kernel<<<BATCH, 256>>>(sth, Wdec, bdec, dec);
    score_kernel<<<ROWS, 256>>>(wgs, dec, cov, v, scores);
    softmax_kernel<<<BATCH, 256>>>(scores, cov, alpha, out_cov, out_alpha);
    context_kernel<<<BATCH, 256>>>(gstar, alpha, out_cimg);
}

// round 11
// speedup vs baseline: 2.4527x; 1.4255x over previous
#include <cuda_runtime.h>
#include <cuda_bf16.h>
#include <math.h>
#include <stdint.h>

// Problem dims (fixed by the dataset)
#define BATCH 32
#define TK    196
#define ROWS  (BATCH * TK)   // 6272 = 49 * 128
#define GFD   4096
#define DH    1024

#define KSPLIT 32            // b1 GEMV k-chunks

// ---------------------------------------------------------------------------
// Scratch (allocation-free rule: __device__ globals)
// ---------------------------------------------------------------------------
__device__ __align__(16) float g_W1[GFD * DH];       // Wg @ Gs (fp32)
__device__ __align__(16) float g_b1[DH];             // bg @ Gs + bgs
__device__ __align__(16) float g_b1part[KSPLIT * DH];
__device__ __align__(16) float g_gstar[ROWS * DH];   // X @ W1 + b1 (fp32)
__device__ __align__(16) float g_wgs[ROWS * DH];     // g_star @ Wgs (fp32)
__device__ __align__(16) float g_dec[BATCH * DH];
__device__ __align__(16) float g_scores[ROWS];
__device__ __align__(16) float g_alpha[ROWS];

// split-bf16 operands
__device__ __align__(16) __nv_bfloat16 g_Xhi[ROWS * GFD];
__device__ __align__(16) __nv_bfloat16 g_Xlo[ROWS * GFD];
__device__ __align__(16) __nv_bfloat16 g_Wghi[GFD * GFD];
__device__ __align__(16) __nv_bfloat16 g_Wglo[GFD * GFD];
__device__ __align__(16) __nv_bfloat16 g_GsThi[DH * GFD];   // Gs^T  [DH, GFD]
__device__ __align__(16) __nv_bfloat16 g_GsTlo[DH * GFD];
__device__ __align__(16) __nv_bfloat16 g_W1Thi[DH * GFD];   // W1^T  [DH, GFD]
__device__ __align__(16) __nv_bfloat16 g_W1Tlo[DH * GFD];
__device__ __align__(16) __nv_bfloat16 g_ghi[ROWS * DH];    // gstar split
__device__ __align__(16) __nv_bfloat16 g_glo[ROWS * DH];
__device__ __align__(16) __nv_bfloat16 g_WgsThi[DH * DH];   // Wgs^T [DH, DH]
__device__ __align__(16) __nv_bfloat16 g_WgsTlo[DH * DH];

// ---------------------------------------------------------------------------
// Helpers (base compute_103 PTX only: mma.sync + cp.async, both sm_80+)
// ---------------------------------------------------------------------------
__device__ __forceinline__ uint32_t smem_u32(const void* p) {
    uint32_t a;
    asm("{ .reg .u64 t; cvta.to.shared.u64 t, %1; cvt.u32.u64 %0, t; }"
        : "=r"(a) : "l"(p));
    return a;
}

__device__ __forceinline__ void cp_async16(void* sptr, const void* gptr) {
    uint32_t s = smem_u32(sptr);
    asm volatile("cp.async.cg.shared.global [%0], [%1], 16;"
                 :: "r"(s), "l"(gptr) : "memory");
}
#define CP_COMMIT() asm volatile("cp.async.commit_group;" ::: "memory")
#define CP_WAIT0()  asm volatile("cp.async.wait_group 0;" ::: "memory")

// m16n8k16 row.col bf16 -> f32
#define MMA16816(c, a, b) \
    asm volatile( \
        "mma.sync.aligned.m16n8k16.row.col.f32.bf16.bf16.f32 " \
        "{%0,%1,%2,%3}, {%4,%5,%6,%7}, {%8,%9}, {%0,%1,%2,%3};" \
        : "+f"((c)[0]), "+f"((c)[1]), "+f"((c)[2]), "+f"((c)[3]) \
        : "r"((a)[0]), "r"((a)[1]), "r"((a)[2]), "r"((a)[3]), \
          "r"((b)[0]), "r"((b)[1]))

// ---------------------------------------------------------------------------
// Tensor-core split-bf16 GEMM: C[M,N] = Ahi/lo[M,K] @ (Bhi/lo[N,K])^T (+bias)
// 128x128 tile/CTA, 8 warps (2x4) each m64xn32, BK=32, cp.async double buffer.
// PAD=40 elems/row: 16B-aligned rows, conflict-free fragment loads.
// M,N % 128 == 0, K % 32 == 0.
// ---------------------------------------------------------------------------
#define PAD 40
#define TILE_ELEMS (128 * PAD)          // one 128x32 tile (padded)
#define STAGE_ELEMS (4 * TILE_ELEMS)    // Ahi, Alo, Bhi, Blo
#define MM_SMEM (2 * STAGE_ELEMS * 2)   // bytes, double buffered = 81920

__global__ __launch_bounds__(256)
void mma_gemm(int M, int N, int K,
              const __nv_bfloat16* __restrict__ Ahi, const __nv_bfloat16* __restrict__ Alo,
              const __nv_bfloat16* __restrict__ Bhi, const __nv_bfloat16* __restrict__ Blo,
              const float* __restrict__ bias, float* __restrict__ C)
{
    extern __shared__ __nv_bfloat16 sm[];
    const int tid  = threadIdx.x;
    const int wid  = tid >> 5;
    const int lane = tid & 31;
    const int g    = lane >> 2;      // 0..7
    const int tig  = lane & 3;       // 0..3
    const int wm   = wid >> 2;       // 0..1  (warp row)
    const int wn   = wid & 3;        // 0..3  (warp col)
    const int m0 = blockIdx.y * 128;
    const int n0 = blockIdx.x * 128;
    const int seg = tid & 3;         // 16B segment within 32-elem K row
    const int lr  = tid >> 2;        // 0..63 (2 passes of 64 rows)

    float acc[4][4][4];
#pragma unroll
    for (int i = 0; i < 4; i++)
#pragma unroll
        for (int j = 0; j < 4; j++)
#pragma unroll
            for (int q = 0; q < 4; q++) acc[i][j][q] = 0.f;

    const int nCh = K / 32;

#define ISSUE(c_, buf_) do {                                                     \
    size_t _k0 = (size_t)(c_) * 32;                                              \
    __nv_bfloat16* _st = sm + (buf_) * STAGE_ELEMS;                              \
    _Pragma("unroll")                                                            \
    for (int _p = 0; _p < 2; _p++) {                                             \
        int _r = lr + _p * 64;                                                   \
        size_t _so = (size_t)_r * PAD + seg * 8;                                 \
        size_t _ga = (size_t)(m0 + _r) * K + _k0 + seg * 8;                      \
        size_t _gb = (size_t)(n0 + _r) * K + _k0 + seg * 8;                      \
        cp_async16(_st + _so,                  Ahi + _ga);                       \
        cp_async16(_st + TILE_ELEMS + _so,     Alo + _ga);                       \
        cp_async16(_st + 2 * TILE_ELEMS + _so, Bhi + _gb);                       \
        cp_async16(_st + 3 * TILE_ELEMS + _so, Blo + _gb);                       \
    }                                                                            \
} while (0)

    ISSUE(0, 0);
    CP_COMMIT();

    for (int c = 0; c < nCh; ++c) {
        const int buf = c & 1;
        CP_WAIT0();
        __syncthreads();                 // buffer `buf` ready; prior compute done
        if (c + 1 < nCh) {
            ISSUE(c + 1, buf ^ 1);
            CP_COMMIT();
        }

        const __nv_bfloat16* sAh = sm + buf * STAGE_ELEMS;
        const __nv_bfloat16* sAl = sAh + TILE_ELEMS;
        const __nv_bfloat16* sBh = sAh + 2 * TILE_ELEMS;
        const __nv_bfloat16* sBl = sAh + 3 * TILE_ELEMS;

#pragma unroll
        for (int ks = 0; ks < 2; ks++) {
            const int kc = ks * 16 + 2 * tig;
            uint32_t ah[4][4], al[4][4], bh[4][2], bl[4][2];
#pragma unroll
            for (int mt = 0; mt < 4; mt++) {
                int r = wm * 64 + mt * 16 + g;
                ah[mt][0] = *(const uint32_t*)(sAh + (size_t)r * PAD + kc);
                ah[mt][1] = *(const uint32_t*)(sAh + (size_t)(r + 8) * PAD + kc);
                ah[mt][2] = *(const uint32_t*)(sAh + (size_t)r * PAD + kc + 8);
                ah[mt][3] = *(const uint32_t*)(sAh + (size_t)(r + 8) * PAD + kc + 8);
                al[mt][0] = *(const uint32_t*)(sAl + (size_t)r * PAD + kc);
                al[mt][1] = *(const uint32_t*)(sAl + (size_t)(r + 8) * PAD + kc);
                al[mt][2] = *(const uint32_t*)(sAl + (size_t)r * PAD + kc + 8);
                al[mt][3] = *(const uint32_t*)(sAl + (size_t)(r + 8) * PAD + kc + 8);
            }
#pragma unroll
            for (int nt = 0; nt < 4; nt++) {
                int r = wn * 32 + nt * 8 + g;
                bh[nt][0] = *(const uint32_t*)(sBh + (size_t)r * PAD + kc);
                bh[nt][1] = *(const uint32_t*)(sBh + (size_t)r * PAD + kc + 8);
                bl[nt][0] = *(const uint32_t*)(sBl + (size_t)r * PAD + kc);
                bl[nt][1] = *(const uint32_t*)(sBl + (size_t)r * PAD + kc + 8);
            }
#pragma unroll
            for (int mt = 0; mt < 4; mt++)
#pragma unroll
                for (int nt = 0; nt < 4; nt++) {
                    MMA16816(acc[mt][nt], ah[mt], bh[nt]);   // hi*hi
                    MMA16816(acc[mt][nt], ah[mt], bl[nt]);   // hi*lo
                    MMA16816(acc[mt][nt], al[mt], bh[nt]);   // lo*hi
                }
        }
        __syncthreads();   // all warps done with `buf` before it is refilled
    }
#undef ISSUE

    // Epilogue: c0=C[g][2tig], c1=C[g][2tig+1], c2=C[g+8][2tig], c3=C[g+8][2tig+1]
#pragma unroll
    for (int mt = 0; mt < 4; mt++) {
#pragma unroll
        for (int nt = 0; nt < 4; nt++) {
            int r  = m0 + wm * 64 + mt * 16 + g;
            int cc = n0 + wn * 32 + nt * 8 + 2 * tig;
            float b0 = bias ? bias[cc]     : 0.f;
            float b1 = bias ? bias[cc + 1] : 0.f;
            float2 o0 = make_float2(acc[mt][nt][0] + b0, acc[mt][nt][1] + b1);
            float2 o1 = make_float2(acc[mt][nt][2] + b0, acc[mt][nt][3] + b1);
            *reinterpret_cast<float2*>(C + (size_t)r * N + cc)       = o0;
            *reinterpret_cast<float2*>(C + (size_t)(r + 8) * N + cc) = o1;
        }
    }
}

// ---------------------------------------------------------------------------
// split fp32 -> (hi, lo) bf16, same layout. n4 = element_count / 4.
// ---------------------------------------------------------------------------
__global__ void split_kernel(const float4* __restrict__ in,
                             uint2* __restrict__ hi, uint2* __restrict__ lo, int n4)
{
    int i = blockIdx.x * blockDim.x + threadIdx.x;
    if (i >= n4) return;
    float4 v = in[i];
    float vv[4] = {v.x, v.y, v.z, v.w};
    unsigned short hs[4], ls[4];
#pragma unroll
    for (int j = 0; j < 4; j++) {
        __nv_bfloat16 h = __float2bfloat16(vv[j]);
        __nv_bfloat16 l = __float2bfloat16(vv[j] - __bfloat162float(h));
        hs[j] = *reinterpret_cast<unsigned short*>(&h);
        ls[j] = *reinterpret_cast<unsigned short*>(&l);
    }
    uint2 H, L;
    H.x = (uint32_t)hs[0] | ((uint32_t)hs[1] << 16);
    H.y = (uint32_t)hs[2] | ((uint32_t)hs[3] << 16);
    L.x = (uint32_t)ls[0] | ((uint32_t)ls[1] << 16);
    L.y = (uint32_t)ls[2] | ((uint32_t)ls[3] << 16);
    hi[i] = H;
    lo[i] = L;
}

// ---------------------------------------------------------------------------
// transpose + split: in fp32 [R,C] -> hiT/loT bf16 [C,R]
// grid (C/32, R/32), block (32, 8)
// ---------------------------------------------------------------------------
__global__ void tsplit_kernel(const float* __restrict__ in,
                              __nv_bfloat16* __restrict__ hiT,
                              __nv_bfloat16* __restrict__ loT, int R, int C)
{
    __shared__ float sh[32][33];
    int c0 = blockIdx.x * 32, r0 = blockIdx.y * 32;
    int tx = threadIdx.x, ty = threadIdx.y;
#pragma unroll
    for (int i = 0; i < 32; i += 8)
        sh[ty + i][tx] = in[(size_t)(r0 + ty + i) * C + c0 + tx];
    __syncthreads();
#pragma unroll
    for (int i = 0; i < 32; i += 8) {
        float v = sh[tx][ty + i];
        __nv_bfloat16 h = __float2bfloat16(v);
        __nv_bfloat16 l = __float2bfloat16(v - __bfloat162float(h));
        size_t o = (size_t)(c0 + ty + i) * R + r0 + tx;
        hiT[o] = h;
        loT[o] = l;
    }
}

// ---------------------------------------------------------------------------
// b1 GEMV, k-split for parallelism (was the #1 hotspot: 301us on grid=4).
// part[kc][j] = sum_{k in chunk kc} bg[k] * Gs[k,j]
// grid (DH/256, KSPLIT), block 256. Then deterministic reduce.
// ---------------------------------------------------------------------------
__global__ void b1_partial_kernel(const float* __restrict__ bg,
                                  const float* __restrict__ Gs,
                                  float* __restrict__ part)
{
    const int j  = blockIdx.x * 256 + threadIdx.x;
    const int kc = blockIdx.y;
    const int k0 = kc * (GFD / KSPLIT);
    float acc = 0.f;
#pragma unroll 8
    for (int k = k0; k < k0 + GFD / KSPLIT; k++)
        acc += bg[k] * Gs[(size_t)k * DH + j];
    part[kc * DH + j] = acc;
}

__global__ void b1_reduce_kernel(const float* __restrict__ part,
                                 const float* __restrict__ bgs,
                                 float* __restrict__ b1)
{
    const int j = blockIdx.x * 256 + threadIdx.x;
    float acc = bgs[j];
#pragma unroll
    for (int kc = 0; kc < KSPLIT; kc++)
        acc += part[kc * DH + j];
    b1[j] = acc;
}

// ---------------------------------------------------------------------------
// dec[b,j] = s[b,:] @ Wdec[:,j] + bdec[j]
// grid (DH/128, BATCH), block 256: 2 threads per output j, k split in half,
// fixed-order combine via shared (deterministic).
// ---------------------------------------------------------------------------
__global__ void dec_kernel(const float* __restrict__ s, const float* __restrict__ Wdec,
                           const float* __restrict__ bdec, float* __restrict__ dec)
{
    const int b    = blockIdx.y;
    const int j    = blockIdx.x * 128 + (threadIdx.x & 127);
    const int half = threadIdx.x >> 7;            // 0 or 1
    const int k0   = half * (DH / 2);

    const float* sb = s + (size_t)b * DH;
    float acc = 0.f;
#pragma unroll 8
    for (int k = k0; k < k0 + DH / 2; k++)
        acc += sb[k] * Wdec[(size_t)k * DH + j];

    __shared__ float red[256];
    red[threadIdx.x] = acc;
    __syncthreads();
    if (half == 0)
        dec[(size_t)b * DH + j] = red[threadIdx.x] + red[threadIdx.x + 128] + bdec[j];
}

// ---------------------------------------------------------------------------
// scores[row] = sum_j tanh(w[row,j] + dec[b,j] + cov[row]) * v[j]
// ---------------------------------------------------------------------------
__global__ void score_kernel(const float* __restrict__ w, const float* __restrict__ dec,
                             const float* __restrict__ cov, const float* __restrict__ v,
                             float* __restrict__ scores)
{
    int row = blockIdx.x;
    int b   = row / TK;
    float c = cov[row];
    const float* wr = w   + (size_t)row * DH;
    const float* db = dec + (size_t)b   * DH;

    float acc = 0.f;
    for (int j = threadIdx.x; j < DH; j += blockDim.x)
        acc += tanhf(wr[j] + db[j] + c) * v[j];

    for (int off = 16; off > 0; off >>= 1)
        acc += __shfl_xor_sync(0xffffffffu, acc, off);

    __shared__ float red[8];
    if ((threadIdx.x & 31) == 0) red[threadIdx.x >> 5] = acc;
    __syncthreads();
    if (threadIdx.x == 0) {
        float s = 0.f;
#pragma unroll
        for (int i = 0; i < 8; i++) s += red[i];
        scores[row] = s;
    }
}

// ---------------------------------------------------------------------------
// Per-batch softmax over TK regions; alpha + coverage_new outputs.
// ---------------------------------------------------------------------------
__global__ void softmax_kernel(const float* __restrict__ scores, const float* __restrict__ cov,
                               float* __restrict__ alpha, float* __restrict__ out_cov,
                               float* __restrict__ out_alpha)
{
    int b = blockIdx.x;
    int t = threadIdx.x;
    __shared__ float sh[256];

    float s = (t < TK) ? scores[b * TK + t] : -3.402823e38f;
    sh[t] = s;
    __syncthreads();
#pragma unroll
    for (int st = 128; st > 0; st >>= 1) {
        if (t < st) sh[t] = fmaxf(sh[t], sh[t + st]);
        __syncthreads();
    }
    float mx = sh[0];
    __syncthreads();

    float e = (t < TK) ? expf(s - mx) : 0.f;
    sh[t] = e;
    __syncthreads();
#pragma unroll
    for (int st = 128; st > 0; st >>= 1) {
        if (t < st) sh[t] += sh[t + st];
        __syncthreads();
    }
    float inv = 1.f / sh[0];

    if (t < TK) {
        float a = e * inv;
        alpha[b * TK + t]     = a;
        out_alpha[b * TK + t] = a;
        out_cov[b * TK + t]   = cov[b * TK + t] + a;
    }
}

// ---------------------------------------------------------------------------
// c_img[b,d] = sum_t alpha[b,t] * g_star[b,t,d]
// ---------------------------------------------------------------------------
__global__ void context_kernel(const float* __restrict__ gstar,
                               const float* __restrict__ alpha, float* __restrict__ cimg)
{
    int b = blockIdx.x;
    __shared__ float a[TK];
    for (int t = threadIdx.x; t < TK; t += blockDim.x)
        a[t] = alpha[b * TK + t];
    __syncthreads();

    for (int d = threadIdx.x; d < DH; d += blockDim.x) {
        const float* g = gstar + (size_t)b * TK * DH + d;
        float acc = 0.f;
#pragma unroll 7
        for (int t = 0; t < TK; t++)
            acc += a[t] * g[(size_t)t * DH];
        cimg[(size_t)b * DH + d] = acc;
    }
}

// ---------------------------------------------------------------------------
// Launcher
// Inputs (metadata order):
//  0 global_features [32,196,4096]  1 s_t_hat [32,1024]  2 coverage_img [32,196,1]
//  3 Wg [4096,4096]  4 bg [4096]  5 Gs [4096,1024]  6 bgs [1024]
//  7 Wgs [1024,1024] 8 Wdec [1024,1024] 9 bdec [1024] 10 v [1024,1]
// Output: c_img [32*1024] | coverage_new [32*196] | alpha [32*196]
// ---------------------------------------------------------------------------
extern "C" void kernel_launch(void* const* d_in, const int* in_sizes, int n_in,
                              void* d_out, int out_size)
{
    const float* X    = (const float*)d_in[0];
    const float* sth  = (const float*)d_in[1];
    const float* cov  = (const float*)d_in[2];
    const float* Wg   = (const float*)d_in[3];
    const float* bg   = (const float*)d_in[4];
    const float* Gs   = (const float*)d_in[5];
    const float* bgs  = (const float*)d_in[6];
    const float* Wgs  = (const float*)d_in[7];
    const float* Wdec = (const float*)d_in[8];
    const float* bdec = (const float*)d_in[9];
    const float* v    = (const float*)d_in[10];

    float* out       = (float*)d_out;
    float* out_cimg  = out;
    float* out_cov   = out + BATCH * DH;
    float* out_alpha = out + BATCH * DH + BATCH * TK;

    float *W1, *b1, *b1part, *gstar, *wgs, *dec, *scores, *alpha;
    cudaGetSymbolAddress((void**)&W1,     g_W1);
    cudaGetSymbolAddress((void**)&b1,     g_b1);
    cudaGetSymbolAddress((void**)&b1part, g_b1part);
    cudaGetSymbolAddress((void**)&gstar,  g_gstar);
    cudaGetSymbolAddress((void**)&wgs,    g_wgs);
    cudaGetSymbolAddress((void**)&dec,    g_dec);
    cudaGetSymbolAddress((void**)&scores, g_scores);
    cudaGetSymbolAddress((void**)&alpha,  g_alpha);

    __nv_bfloat16 *Xhi, *Xlo, *Wghi, *Wglo, *GsThi, *GsTlo, *W1Thi, *W1Tlo,
                  *ghi, *glo, *WgsThi, *WgsTlo;
    cudaGetSymbolAddress((void**)&Xhi,    g_Xhi);
    cudaGetSymbolAddress((void**)&Xlo,    g_Xlo);
    cudaGetSymbolAddress((void**)&Wghi,   g_Wghi);
    cudaGetSymbolAddress((void**)&Wglo,   g_Wglo);
    cudaGetSymbolAddress((void**)&GsThi,  g_GsThi);
    cudaGetSymbolAddress((void**)&GsTlo,  g_GsTlo);
    cudaGetSymbolAddress((void**)&W1Thi,  g_W1Thi);
    cudaGetSymbolAddress((void**)&W1Tlo,  g_W1Tlo);
    cudaGetSymbolAddress((void**)&ghi,    g_ghi);
    cudaGetSymbolAddress((void**)&glo,    g_glo);
    cudaGetSymbolAddress((void**)&WgsThi, g_WgsThi);
    cudaGetSymbolAddress((void**)&WgsTlo, g_WgsTlo);

    cudaFuncSetAttribute(mma_gemm, cudaFuncAttributeMaxDynamicSharedMemorySize, MM_SMEM);

    // --- operand prep ---
    split_kernel<<<(GFD * GFD / 4 + 255) / 256, 256>>>(
        (const float4*)Wg, (uint2*)Wghi, (uint2*)Wglo, GFD * GFD / 4);
    tsplit_kernel<<<dim3(DH / 32, GFD / 32), dim3(32, 8)>>>(Gs, GsThi, GsTlo, GFD, DH);
    split_kernel<<<(ROWS * GFD / 4 + 255) / 256, 256>>>(
        (const float4*)X, (uint2*)Xhi, (uint2*)Xlo, ROWS * GFD / 4);
    b1_partial_kernel<<<dim3(DH / 256, KSPLIT), 256>>>(bg, Gs, b1part);
    b1_reduce_kernel<<<DH / 256, 256>>>(b1part, bgs, b1);
    tsplit_kernel<<<dim3(DH / 32, DH / 32), dim3(32, 8)>>>(Wgs, WgsThi, WgsTlo, DH, DH);

    // 1) W1 = Wg @ Gs              [4096,1024], K=4096
    mma_gemm<<<dim3(DH / 128, GFD / 128), 256, MM_SMEM>>>(
        GFD, DH, GFD, Wghi, Wglo, GsThi, GsTlo, nullptr, W1);
    tsplit_kernel<<<dim3(DH / 32, GFD / 32), dim3(32, 8)>>>(W1, W1Thi, W1Tlo, GFD, DH);

    // 2) g_star = X @ W1 + b1      [6272,1024], K=4096
    mma_gemm<<<dim3(DH / 128, ROWS / 128), 256, MM_SMEM>>>(
        ROWS, DH, GFD, Xhi, Xlo, W1Thi, W1Tlo, b1, gstar);
    split_kernel<<<(ROWS * DH / 4 + 255) / 256, 256>>>(
        (const float4*)gstar, (uint2*)ghi, (uint2*)glo, ROWS * DH / 4);

    // 3) w = g_star @ Wgs          [6272,1024], K=1024
    mma_gemm<<<dim3(DH / 128, ROWS / 128), 256, MM_SMEM>>>(
        ROWS, DH, DH, ghi, glo, WgsThi, WgsTlo, nullptr, wgs);

    // 4) epilogue chain
    dec_kernel<<<dim3(DH / 128, BATCH), 256>>>(sth, Wdec, bdec, dec);
    score_kernel<<<ROWS, 256>>>(wgs, dec, cov, v, scores);
    softmax_kernel<<<BATCH, 256>>>(scores, cov, alpha, out_cov, out_alpha);
    context_kernel<<<BATCH, 256>>>(gstar, alpha, out_cimg);
}

// round 15
// speedup vs baseline: 2.6668x; 1.0873x over previous
#include <cuda_runtime.h>
#include <cuda_bf16.h>
#include <math.h>
#include <stdint.h>

// Problem dims (fixed by the dataset)
#define BATCH 32
#define TK    196
#define ROWS  (BATCH * TK)   // 6272 = 49 * 128
#define GFD   4096
#define DH    1024

#define KSPLIT 128           // b1 GEMV k-chunks
#define NSPLIT 8             // score partial chunks (DH/128)

// ---------------------------------------------------------------------------
// Scratch (allocation-free rule: __device__ globals)
// ---------------------------------------------------------------------------
__device__ __align__(16) float g_W1[GFD * DH];       // Wg @ Gs (fp32)
__device__ __align__(16) float g_b1[DH];             // bg @ Gs + bgs
__device__ __align__(16) float g_b1part[KSPLIT * DH];
__device__ __align__(16) float g_gstar[ROWS * DH];   // X @ W1 + b1 (fp32)
__device__ __align__(16) float g_dec[BATCH * DH];
__device__ __align__(16) float g_spart[ROWS * NSPLIT];
__device__ __align__(16) float g_scores[ROWS];
__device__ __align__(16) float g_alpha[ROWS];

// split-bf16 operands
__device__ __align__(16) __nv_bfloat16 g_Xhi[ROWS * GFD];
__device__ __align__(16) __nv_bfloat16 g_Xlo[ROWS * GFD];
__device__ __align__(16) __nv_bfloat16 g_Wghi[GFD * GFD];
__device__ __align__(16) __nv_bfloat16 g_Wglo[GFD * GFD];
__device__ __align__(16) __nv_bfloat16 g_GsThi[DH * GFD];   // Gs^T  [DH, GFD]
__device__ __align__(16) __nv_bfloat16 g_GsTlo[DH * GFD];
__device__ __align__(16) __nv_bfloat16 g_W1Thi[DH * GFD];   // W1^T  [DH, GFD]
__device__ __align__(16) __nv_bfloat16 g_W1Tlo[DH * GFD];
__device__ __align__(16) __nv_bfloat16 g_ghi[ROWS * DH];    // gstar split
__device__ __align__(16) __nv_bfloat16 g_glo[ROWS * DH];
__device__ __align__(16) __nv_bfloat16 g_WgsThi[DH * DH];   // Wgs^T [DH, DH]
__device__ __align__(16) __nv_bfloat16 g_WgsTlo[DH * DH];

// ---------------------------------------------------------------------------
// Helpers (base compute_103 PTX only: mma.sync + cp.async + ldmatrix)
// ---------------------------------------------------------------------------
__device__ __forceinline__ uint32_t smem_u32(const void* p) {
    uint32_t a;
    asm("{ .reg .u64 t; cvta.to.shared.u64 t, %1; cvt.u32.u64 %0, t; }"
        : "=r"(a) : "l"(p));
    return a;
}

__device__ __forceinline__ void cp_async16(void* sptr, const void* gptr) {
    uint32_t s = smem_u32(sptr);
    asm volatile("cp.async.cg.shared.global [%0], [%1], 16;"
                 :: "r"(s), "l"(gptr) : "memory");
}
#define CP_COMMIT() asm volatile("cp.async.commit_group;" ::: "memory")
#define CP_WAIT0()  asm volatile("cp.async.wait_group 0;" ::: "memory")

#define LDSM_X4(r0, r1, r2, r3, addr) \
    asm volatile("ldmatrix.sync.aligned.m8n8.x4.shared.b16 {%0,%1,%2,%3}, [%4];" \
        : "=r"(r0), "=r"(r1), "=r"(r2), "=r"(r3) : "r"(addr))

// m16n8k16 row.col bf16 -> f32
#define MMA16816(c, a, b) \
    asm volatile( \
        "mma.sync.aligned.m16n8k16.row.col.f32.bf16.bf16.f32 " \
        "{%0,%1,%2,%3}, {%4,%5,%6,%7}, {%8,%9}, {%0,%1,%2,%3};" \
        : "+f"((c)[0]), "+f"((c)[1]), "+f"((c)[2]), "+f"((c)[3]) \
        : "r"((a)[0]), "r"((a)[1]), "r"((a)[2]), "r"((a)[3]), \
          "r"((b)[0]), "r"((b)[1]))

// ---------------------------------------------------------------------------
// Tensor-core split-bf16 GEMM: C[M,N] = Ahi/lo[M,K] @ (Bhi/lo[N,K])^T (+bias)
// 128x128 tile/CTA, 8 warps (2x4) each m64xn32, BK=32, cp.async double buffer,
// ldmatrix fragment loads.
//   A tiles [m][k]: plain ldmatrix.x4, subs = {m0-7,m8-15} x {k0-7,k8-15}.
//   B tiles [n][k]: plain ldmatrix.x4 (k contiguous at fixed n == .col B frag;
//                   .trans would be for [k][n] storage).
// Optional fused outputs:
//   Chi/Clo non-null -> also write bf16 split of C (same layout).
//   spart non-null   -> score mode: skip C, write per-(row, n-chunk) partials of
//                       sum_j tanh(C + dec + cov) * v  into spart[row*NSPLIT + bx].
// M,N % 128 == 0, K % 32 == 0.
// ---------------------------------------------------------------------------
#define PAD 40
#define TILE_ELEMS (128 * PAD)          // one 128x32 tile (padded)
#define STAGE_ELEMS (4 * TILE_ELEMS)    // Ahi, Alo, Bhi, Blo
#define MM_SMEM (2 * STAGE_ELEMS * 2)   // bytes, double buffered = 81920
#define PADR 132                        // score-epilogue smem row stride (floats)

__global__ __launch_bounds__(256)
void mma_gemm(int M, int N, int K,
              const __nv_bfloat16* __restrict__ Ahi, const __nv_bfloat16* __restrict__ Alo,
              const __nv_bfloat16* __restrict__ Bhi, const __nv_bfloat16* __restrict__ Blo,
              const float* __restrict__ bias, float* __restrict__ C,
              __nv_bfloat16* __restrict__ Chi, __nv_bfloat16* __restrict__ Clo,
              float* __restrict__ spart, const float* __restrict__ decv,
              const float* __restrict__ covv, const float* __restrict__ vvec)
{
    extern __shared__ __nv_bfloat16 sm[];
    const uint32_t smb = smem_u32(sm);
    const int tid  = threadIdx.x;
    const int wid  = tid >> 5;
    const int lane = tid & 31;
    const int g    = lane >> 2;      // 0..7
    const int tig  = lane & 3;       // 0..3
    const int wm   = wid >> 2;       // 0..1  (warp row)
    const int wn   = wid & 3;        // 0..3  (warp col)
    const int m0 = blockIdx.y * 128;
    const int n0 = blockIdx.x * 128;
    const int seg = tid & 3;         // 16B segment within 32-elem K row
    const int lr  = tid >> 2;        // 0..63 (2 passes of 64 rows)

    // ldmatrix lane addressing (4 subs of 8 lanes each)
    const int sub = lane >> 3;       // 0..3 (matrix select)
    const int q   = lane & 7;        // row within matrix
    const int arow = (sub & 1) * 8 + q;        // A: {m0-7, m8-15} x {k0-7, k8-15}
    const int acol = (sub >> 1) * 8;
    const int brow = (sub >> 1) * 8 + q;       // B: {n0-7, n8-15} select by sub>>1
    const int bcol = (sub & 1) * 8;            //    {k0-7, k8-15} select by sub&1

    float acc[4][4][4];
#pragma unroll
    for (int i = 0; i < 4; i++)
#pragma unroll
        for (int j = 0; j < 4; j++)
#pragma unroll
            for (int p = 0; p < 4; p++) acc[i][j][p] = 0.f;

    const int nCh = K / 32;

#define ISSUE(c_, buf_) do {                                                     \
    size_t _k0 = (size_t)(c_) * 32;                                              \
    __nv_bfloat16* _st = sm + (buf_) * STAGE_ELEMS;                              \
    _Pragma("unroll")                                                            \
    for (int _p = 0; _p < 2; _p++) {                                             \
        int _r = lr + _p * 64;                                                   \
        size_t _so = (size_t)_r * PAD + seg * 8;                                 \
        size_t _ga = (size_t)(m0 + _r) * K + _k0 + seg * 8;                      \
        size_t _gb = (size_t)(n0 + _r) * K + _k0 + seg * 8;                      \
        cp_async16(_st + _so,                  Ahi + _ga);                       \
        cp_async16(_st + TILE_ELEMS + _so,     Alo + _ga);                       \
        cp_async16(_st + 2 * TILE_ELEMS + _so, Bhi + _gb);                       \
        cp_async16(_st + 3 * TILE_ELEMS + _so, Blo + _gb);                       \
    }                                                                            \
} while (0)

    ISSUE(0, 0);
    CP_COMMIT();

    for (int c = 0; c < nCh; ++c) {
        const int buf = c & 1;
        CP_WAIT0();
        __syncthreads();                 // buffer `buf` ready; prior compute done
        if (c + 1 < nCh) {
            ISSUE(c + 1, buf ^ 1);
            CP_COMMIT();
        }

        const uint32_t sAh = smb + buf * STAGE_ELEMS * 2;
        const uint32_t sAl = sAh + TILE_ELEMS * 2;
        const uint32_t sBh = sAh + 2 * TILE_ELEMS * 2;
        const uint32_t sBl = sAh + 3 * TILE_ELEMS * 2;

#pragma unroll
        for (int ks = 0; ks < 2; ks++) {
            const int kc = ks * 16;
            uint32_t ah[4][4], al[4][4], bh[4][2], bl[4][2];
#pragma unroll
            for (int mt = 0; mt < 4; mt++) {
                uint32_t off = ((wm * 64 + mt * 16 + arow) * PAD + kc + acol) * 2;
                LDSM_X4(ah[mt][0], ah[mt][1], ah[mt][2], ah[mt][3], sAh + off);
                LDSM_X4(al[mt][0], al[mt][1], al[mt][2], al[mt][3], sAl + off);
            }
#pragma unroll
            for (int p = 0; p < 2; p++) {
                uint32_t off = ((wn * 32 + p * 16 + brow) * PAD + kc + bcol) * 2;
                // plain (non-trans) ldmatrix: [n][k] storage gives .col B frag
                LDSM_X4(bh[2*p][0], bh[2*p][1], bh[2*p+1][0], bh[2*p+1][1], sBh + off);
                LDSM_X4(bl[2*p][0], bl[2*p][1], bl[2*p+1][0], bl[2*p+1][1], sBl + off);
            }
#pragma unroll
            for (int mt = 0; mt < 4; mt++)
#pragma unroll
                for (int nt = 0; nt < 4; nt++) {
                    MMA16816(acc[mt][nt], ah[mt], bh[nt]);   // hi*hi
                    MMA16816(acc[mt][nt], ah[mt], bl[nt]);   // hi*lo
                    MMA16816(acc[mt][nt], al[mt], bh[nt]);   // lo*hi
                }
        }
        __syncthreads();   // all warps done with `buf` before it is refilled
    }
#undef ISSUE

    if (spart == nullptr) {
        // ---- standard epilogue: bias add, fp32 (+ optional bf16 split) stores
#pragma unroll
        for (int mt = 0; mt < 4; mt++) {
#pragma unroll
            for (int nt = 0; nt < 4; nt++) {
                int r  = m0 + wm * 64 + mt * 16 + g;
                int cc = n0 + wn * 32 + nt * 8 + 2 * tig;
                float b0 = bias ? bias[cc]     : 0.f;
                float b1 = bias ? bias[cc + 1] : 0.f;
                float o00 = acc[mt][nt][0] + b0, o01 = acc[mt][nt][1] + b1;
                float o10 = acc[mt][nt][2] + b0, o11 = acc[mt][nt][3] + b1;
                *reinterpret_cast<float2*>(C + (size_t)r * N + cc)       = make_float2(o00, o01);
                *reinterpret_cast<float2*>(C + (size_t)(r + 8) * N + cc) = make_float2(o10, o11);
                if (Chi) {
                    float ov[4] = {o00, o01, o10, o11};
                    unsigned short hs[4], ls[4];
#pragma unroll
                    for (int e = 0; e < 4; e++) {
                        __nv_bfloat16 h = __float2bfloat16(ov[e]);
                        __nv_bfloat16 l = __float2bfloat16(ov[e] - __bfloat162float(h));
                        hs[e] = *reinterpret_cast<unsigned short*>(&h);
                        ls[e] = *reinterpret_cast<unsigned short*>(&l);
                    }
                    uint32_t* Hp0 = reinterpret_cast<uint32_t*>(Chi + (size_t)r * N + cc);
                    uint32_t* Hp1 = reinterpret_cast<uint32_t*>(Chi + (size_t)(r + 8) * N + cc);
                    uint32_t* Lp0 = reinterpret_cast<uint32_t*>(Clo + (size_t)r * N + cc);
                    uint32_t* Lp1 = reinterpret_cast<uint32_t*>(Clo + (size_t)(r + 8) * N + cc);
                    *Hp0 = (uint32_t)hs[0] | ((uint32_t)hs[1] << 16);
                    *Hp1 = (uint32_t)hs[2] | ((uint32_t)hs[3] << 16);
                    *Lp0 = (uint32_t)ls[0] | ((uint32_t)ls[1] << 16);
                    *Lp1 = (uint32_t)ls[2] | ((uint32_t)ls[3] << 16);
                }
            }
        }
    } else {
        // ---- score epilogue: stage w tile in smem, reduce tanh(w+dec+cov)*v
        float* st  = reinterpret_cast<float*>(sm);          // [128][PADR]
        float* red = st + 128 * PADR;                       // [256]
#pragma unroll
        for (int mt = 0; mt < 4; mt++)
#pragma unroll
            for (int nt = 0; nt < 4; nt++) {
                int rl = wm * 64 + mt * 16 + g;
                int cl = wn * 32 + nt * 8 + 2 * tig;
                st[rl * PADR + cl]           = acc[mt][nt][0];
                st[rl * PADR + cl + 1]       = acc[mt][nt][1];
                st[(rl + 8) * PADR + cl]     = acc[mt][nt][2];
                st[(rl + 8) * PADR + cl + 1] = acc[mt][nt][3];
            }
        __syncthreads();

        const int rl    = tid >> 1;          // 0..127
        const int halfc = (tid & 1) * 64;
        const int grow  = m0 + rl;
        const int b     = grow / TK;
        const float cv  = covv[grow];
        const float* db = decv + (size_t)b * DH;
        float s = 0.f;
#pragma unroll 8
        for (int e = 0; e < 64; e++) {
            int cc = halfc + e;
            int gc = n0 + cc;
            s += tanhf(st[rl * PADR + cc] + db[gc] + cv) * vvec[gc];
        }
        red[tid] = s;
        __syncthreads();
        if ((tid & 1) == 0)
            spart[(size_t)grow * NSPLIT + blockIdx.x] = red[tid] + red[tid + 1];
    }
}

// ---------------------------------------------------------------------------
// split fp32 -> (hi, lo) bf16, same layout. n4 = element_count / 4.
// ---------------------------------------------------------------------------
__global__ void split_kernel(const float4* __restrict__ in,
                             uint2* __restrict__ hi, uint2* __restrict__ lo, int n4)
{
    int i = blockIdx.x * blockDim.x + threadIdx.x;
    if (i >= n4) return;
    float4 v = in[i];
    float vv[4] = {v.x, v.y, v.z, v.w};
    unsigned short hs[4], ls[4];
#pragma unroll
    for (int j = 0; j < 4; j++) {
        __nv_bfloat16 h = __float2bfloat16(vv[j]);
        __nv_bfloat16 l = __float2bfloat16(vv[j] - __bfloat162float(h));
        hs[j] = *reinterpret_cast<unsigned short*>(&h);
        ls[j] = *reinterpret_cast<unsigned short*>(&l);
    }
    uint2 H, L;
    H.x = (uint32_t)hs[0] | ((uint32_t)hs[1] << 16);
    H.y = (uint32_t)hs[2] | ((uint32_t)hs[3] << 16);
    L.x = (uint32_t)ls[0] | ((uint32_t)ls[1] << 16);
    L.y = (uint32_t)ls[2] | ((uint32_t)ls[3] << 16);
    hi[i] = H;
    lo[i] = L;
}

// ---------------------------------------------------------------------------
// transpose + split: in fp32 [R,C] -> hiT/loT bf16 [C,R]
// grid (C/32, R/32), block (32, 8)
// ---------------------------------------------------------------------------
__global__ void tsplit_kernel(const float* __restrict__ in,
                              __nv_bfloat16* __restrict__ hiT,
                              __nv_bfloat16* __restrict__ loT, int R, int C)
{
    __shared__ float sh[32][33];
    int c0 = blockIdx.x * 32, r0 = blockIdx.y * 32;
    int tx = threadIdx.x, ty = threadIdx.y;
#pragma unroll
    for (int i = 0; i < 32; i += 8)
        sh[ty + i][tx] = in[(size_t)(r0 + ty + i) * C + c0 + tx];
    __syncthreads();
#pragma unroll
    for (int i = 0; i < 32; i += 8) {
        float v = sh[tx][ty + i];
        __nv_bfloat16 h = __float2bfloat16(v);
        __nv_bfloat16 l = __float2bfloat16(v - __bfloat162float(h));
        size_t o = (size_t)(c0 + ty + i) * R + r0 + tx;
        hiT[o] = h;
        loT[o] = l;
    }
}

// ---------------------------------------------------------------------------
// b1 GEMV, k-split for parallelism. part[kc][j] = sum_chunk bg[k]*Gs[k,j]
// ---------------------------------------------------------------------------
__global__ void b1_partial_kernel(const float* __restrict__ bg,
                                  const float* __restrict__ Gs,
                                  float* __restrict__ part)
{
    const int j  = blockIdx.x * 256 + threadIdx.x;
    const int kc = blockIdx.y;
    const int k0 = kc * (GFD / KSPLIT);
    float acc = 0.f;
#pragma unroll
    for (int k = k0; k < k0 + GFD / KSPLIT; k++)
        acc += bg[k] * Gs[(size_t)k * DH + j];
    part[kc * DH + j] = acc;
}

__global__ void b1_reduce_kernel(const float* __restrict__ part,
                                 const float* __restrict__ bgs,
                                 float* __restrict__ b1)
{
    const int j = blockIdx.x * 256 + threadIdx.x;
    float acc = bgs[j];
#pragma unroll
    for (int kc = 0; kc < KSPLIT; kc++)
        acc += part[kc * DH + j];
    b1[j] = acc;
}

// ---------------------------------------------------------------------------
// dec[b,j] = s[b,:] @ Wdec[:,j] + bdec[j]
// grid (DH/128, BATCH), block 256: 2 threads per output j.
// ---------------------------------------------------------------------------
__global__ void dec_kernel(const float* __restrict__ s, const float* __restrict__ Wdec,
                           const float* __restrict__ bdec, float* __restrict__ dec)
{
    const int b    = blockIdx.y;
    const int j    = blockIdx.x * 128 + (threadIdx.x & 127);
    const int half = threadIdx.x >> 7;            // 0 or 1
    const int k0   = half * (DH / 2);

    const float* sb = s + (size_t)b * DH;
    float acc = 0.f;
#pragma unroll 8
    for (int k = k0; k < k0 + DH / 2; k++)
        acc += sb[k] * Wdec[(size_t)k * DH + j];

    __shared__ float red[256];
    red[threadIdx.x] = acc;
    __syncthreads();
    if (half == 0)
        dec[(size_t)b * DH + j] = red[threadIdx.x] + red[threadIdx.x + 128] + bdec[j];
}

// ---------------------------------------------------------------------------
// scores[row] = sum over NSPLIT partials
// ---------------------------------------------------------------------------
__global__ void score_reduce_kernel(const float* __restrict__ part,
                                    float* __restrict__ scores)
{
    int r = blockIdx.x * 256 + threadIdx.x;
    if (r >= ROWS) return;
    float s = 0.f;
#pragma unroll
    for (int i = 0; i < NSPLIT; i++)
        s += part[(size_t)r * NSPLIT + i];
    scores[r] = s;
}

// ---------------------------------------------------------------------------
// Per-batch softmax over TK regions; alpha + coverage_new outputs.
// ---------------------------------------------------------------------------
__global__ void softmax_kernel(const float* __restrict__ scores, const float* __restrict__ cov,
                               float* __restrict__ alpha, float* __restrict__ out_cov,
                               float* __restrict__ out_alpha)
{
    int b = blockIdx.x;
    int t = threadIdx.x;
    __shared__ float sh[256];

    float s = (t < TK) ? scores[b * TK + t] : -3.402823e38f;
    sh[t] = s;
    __syncthreads();
#pragma unroll
    for (int st = 128; st > 0; st >>= 1) {
        if (t < st) sh[t] = fmaxf(sh[t], sh[t + st]);
        __syncthreads();
    }
    float mx = sh[0];
    __syncthreads();

    float e = (t < TK) ? expf(s - mx) : 0.f;
    sh[t] = e;
    __syncthreads();
#pragma unroll
    for (int st = 128; st > 0; st >>= 1) {
        if (t < st) sh[t] += sh[t + st];
        __syncthreads();
    }
    float inv = 1.f / sh[0];

    if (t < TK) {
        float a = e * inv;
        alpha[b * TK + t]     = a;
        out_alpha[b * TK + t] = a;
        out_cov[b * TK + t]   = cov[b * TK + t] + a;
    }
}

// ---------------------------------------------------------------------------
// c_img[b,d] = sum_t alpha[b,t] * g_star[b,t,d]
// ---------------------------------------------------------------------------
__global__ void context_kernel(const float* __restrict__ gstar,
                               const float* __restrict__ alpha, float* __restrict__ cimg)
{
    int b = blockIdx.x;
    __shared__ float a[TK];
    for (int t = threadIdx.x; t < TK; t += blockDim.x)
        a[t] = alpha[b * TK + t];
    __syncthreads();

    for (int d = threadIdx.x; d < DH; d += blockDim.x) {
        const float* g = gstar + (size_t)b * TK * DH + d;
        float acc = 0.f;
#pragma unroll 7
        for (int t = 0; t < TK; t++)
            acc += a[t] * g[(size_t)t * DH];
        cimg[(size_t)b * DH + d] = acc;
    }
}

// ---------------------------------------------------------------------------
// Launcher
// Inputs (metadata order):
//  0 global_features [32,196,4096]  1 s_t_hat [32,1024]  2 coverage_img [32,196,1]
//  3 Wg [4096,4096]  4 bg [4096]  5 Gs [4096,1024]  6 bgs [1024]
//  7 Wgs [1024,1024] 8 Wdec [1024,1024] 9 bdec [1024] 10 v [1024,1]
// Output: c_img [32*1024] | coverage_new [32*196] | alpha [32*196]
// ---------------------------------------------------------------------------
extern "C" void kernel_launch(void* const* d_in, const int* in_sizes, int n_in,
                              void* d_out, int out_size)
{
    const float* X    = (const float*)d_in[0];
    const float* sth  = (const float*)d_in[1];
    const float* cov  = (const float*)d_in[2];
    const float* Wg   = (const float*)d_in[3];
    const float* bg   = (const float*)d_in[4];
    const float* Gs   = (const float*)d_in[5];
    const float* bgs  = (const float*)d_in[6];
    const float* Wgs  = (const float*)d_in[7];
    const float* Wdec = (const float*)d_in[8];
    const float* bdec = (const float*)d_in[9];
    const float* v    = (const float*)d_in[10];

    float* out       = (float*)d_out;
    float* out_cimg  = out;
    float* out_cov   = out + BATCH * DH;
    float* out_alpha = out + BATCH * DH + BATCH * TK;

    float *W1, *b1, *b1part, *gstar, *dec, *spart, *scores, *alpha;
    cudaGetSymbolAddress((void**)&W1,     g_W1);
    cudaGetSymbolAddress((void**)&b1,     g_b1);
    cudaGetSymbolAddress((void**)&b1part, g_b1part);
    cudaGetSymbolAddress((void**)&gstar,  g_gstar);
    cudaGetSymbolAddress((void**)&dec,    g_dec);
    cudaGetSymbolAddress((void**)&spart,  g_spart);
    cudaGetSymbolAddress((void**)&scores, g_scores);
    cudaGetSymbolAddress((void**)&alpha,  g_alpha);

    __nv_bfloat16 *Xhi, *Xlo, *Wghi, *Wglo, *GsThi, *GsTlo, *W1Thi, *W1Tlo,
                  *ghi, *glo, *WgsThi, *WgsTlo;
    cudaGetSymbolAddress((void**)&Xhi,    g_Xhi);
    cudaGetSymbolAddress((void**)&Xlo,    g_Xlo);
    cudaGetSymbolAddress((void**)&Wghi,   g_Wghi);
    cudaGetSymbolAddress((void**)&Wglo,   g_Wglo);
    cudaGetSymbolAddress((void**)&GsThi,  g_GsThi);
    cudaGetSymbolAddress((void**)&GsTlo,  g_GsTlo);
    cudaGetSymbolAddress((void**)&W1Thi,  g_W1Thi);
    cudaGetSymbolAddress((void**)&W1Tlo,  g_W1Tlo);
    cudaGetSymbolAddress((void**)&ghi,    g_ghi);
    cudaGetSymbolAddress((void**)&glo,    g_glo);
    cudaGetSymbolAddress((void**)&WgsThi, g_WgsThi);
    cudaGetSymbolAddress((void**)&WgsTlo, g_WgsTlo);

    cudaFuncSetAttribute(mma_gemm, cudaFuncAttributeMaxDynamicSharedMemorySize, MM_SMEM);

    // --- operand prep ---
    split_kernel<<<(GFD * GFD / 4 + 255) / 256, 256>>>(
        (const float4*)Wg, (uint2*)Wghi, (uint2*)Wglo, GFD * GFD / 4);
    tsplit_kernel<<<dim3(DH / 32, GFD / 32), dim3(32, 8)>>>(Gs, GsThi, GsTlo, GFD, DH);
    split_kernel<<<(ROWS * GFD / 4 + 255) / 256, 256>>>(
        (const float4*)X, (uint2*)Xhi, (uint2*)Xlo, ROWS * GFD / 4);
    b1_partial_kernel<<<dim3(DH / 256, KSPLIT), 256>>>(bg, Gs, b1part);
    b1_reduce_kernel<<<DH / 256, 256>>>(b1part, bgs, b1);
    tsplit_kernel<<<dim3(DH / 32, DH / 32), dim3(32, 8)>>>(Wgs, WgsThi, WgsTlo, DH, DH);

    // 1) W1 = Wg @ Gs              [4096,1024], K=4096
    mma_gemm<<<dim3(DH / 128, GFD / 128), 256, MM_SMEM>>>(
        GFD, DH, GFD, Wghi, Wglo, GsThi, GsTlo, nullptr, W1,
        nullptr, nullptr, nullptr, nullptr, nullptr, nullptr);
    tsplit_kernel<<<dim3(DH / 32, GFD / 32), dim3(32, 8)>>>(W1, W1Thi, W1Tlo, GFD, DH);

    // 2) g_star = X @ W1 + b1      [6272,1024], K=4096  (+ fused bf16 split)
    mma_gemm<<<dim3(DH / 128, ROWS / 128), 256, MM_SMEM>>>(
        ROWS, DH, GFD, Xhi, Xlo, W1Thi, W1Tlo, b1, gstar,
        ghi, glo, nullptr, nullptr, nullptr, nullptr);

    // 3) dec then w = g_star @ Wgs with fused score partials
    dec_kernel<<<dim3(DH / 128, BATCH), 256>>>(sth, Wdec, bdec, dec);
    mma_gemm<<<dim3(DH / 128, ROWS / 128), 256, MM_SMEM>>>(
        ROWS, DH, DH, ghi, glo, WgsThi, WgsTlo, nullptr, nullptr,
        nullptr, nullptr, spart, dec, cov, v);

    // 4) final chain
    score_reduce_kernel<<<(ROWS + 255) / 256, 256>>>(spart, scores);
    softmax_kernel<<<BATCH, 256>>>(scores, cov, alpha, out_cov, out_alpha);
    context_kernel<<<BATCH, 256>>>(gstar, alpha, out_cimg);
}